// round 12
// baseline (speedup 1.0000x reference)
#include <cuda_runtime.h>
#include <cstdint>

typedef unsigned long long ULL;

// Problem constants
constexpr int Bz = 16, C = 64, H = 64, W = 64;
constexpr int N  = Bz * H * W;     // 65536 rows
constexpr int K  = 1024;           // codes
constexpr int HW = H * W;          // 4096
constexpr int CHW = C * HW;        // 262144

// argmin tiling: 128 rows per CTA x 8 chunks of 128 codes
constexpr int TM  = 128;
constexpr int CH  = 128;
constexpr int NCH = K / CH;        // 8

// int8 quantization scales
constexpr float TQ = 130048.0f;    // 127*1024: |e| <= 1/1024 -> e*TQ in [-127,127]

// smem pitches (u32)
constexpr int PA = 17;             // A tile pitch: conflict-free
constexpr int PB = 20;             // B tile pitch: 16B-aligned cp.async dst, 2-way max

// Score key: val = fma(-2/(s_r*TQ), S_int, 0.3 + en). Row-monotone transform of
// d, always positive (0.3 > max 2|S| ~ 0.19+) -> float bits order-preserving.
// key = (valbits & ~0x7FF) | code -> min is lexicographic (val, lowest code).
constexpr float VAL_BIAS = 0.3f;
// Flag window: int8 quantization noise on d (rms ~3.6e-5; exact int accumulate,
// exact I2F since |S_int| < 2^23) at ~10 sigma + key quantization (<=6.1e-5).
constexpr float EPS_TIE = 3.7e-4f;

// Device scratch (no allocations allowed)
__device__ int      g_idx[N];
__device__ float    g_enorm[K];            // exact ||e||^2 (reference rounding)
__device__ float    g_ens[K];              // VAL_BIAS + ||e||^2
__device__ uint32_t g_embq[K * 16];        // int8-packed emb, [code][kk] 4/u32
__device__ float    g_zn[N];               // exact ||z||^2 (reference order)
__device__ int      g_repair_rows[N];
__device__ int      g_repair_count;
__device__ int      g_repair_tick;
__device__ int      g_gather_done;
__device__ double   g_partials[1024];

__device__ __forceinline__ uint32_t smem_u32(const void* p) {
    uint32_t a;
    asm("{ .reg .u64 t; cvta.to.shared.u64 t, %1; cvt.u32.u64 %0, t; }" : "=r"(a) : "l"(p));
    return a;
}
__device__ __forceinline__ void cp_async16(uint32_t dst, const void* src) {
    asm volatile("cp.async.cg.shared.global [%0], [%1], 16;\n" :: "r"(dst), "l"(src));
}
__device__ __forceinline__ ULL u64min(ULL a, ULL b) { return a < b ? a : b; }
__device__ __forceinline__ uint32_t pack_q4(int q0, int q1, int q2, int q3) {
    return (uint32_t)(q0 & 0xFF) | ((uint32_t)(q1 & 0xFF) << 8) |
           ((uint32_t)(q2 & 0xFF) << 16) | ((uint32_t)q3 << 24);
}

// ---------------------------------------------------------------------------
// Kernel 0: ||e||^2 (reference rounding), biased norms, int8 emb, counters.
// ---------------------------------------------------------------------------
__global__ void prep_kernel(const float* __restrict__ emb) {
    if (blockIdx.x == 0 && threadIdx.x == 0) {
        g_repair_count = 0; g_repair_tick = 0; g_gather_done = 0;
    }
    int code = blockIdx.x * blockDim.x + threadIdx.x;   // 0..1023
    if (code < K) {
        const float* e = emb + code * C;
        float acc = 0.f;
        #pragma unroll
        for (int c = 0; c < C; c++) {
            float v = e[c];
            acc = __fadd_rn(acc, __fmul_rn(v, v));
        }
        g_enorm[code] = acc;
        g_ens[code]   = VAL_BIAS + acc;
        uint32_t* o = g_embq + code * 16;
        #pragma unroll
        for (int kk = 0; kk < 16; kk++) {
            int q0 = __float2int_rn(e[4 * kk + 0] * TQ);
            int q1 = __float2int_rn(e[4 * kk + 1] * TQ);
            int q2 = __float2int_rn(e[4 * kk + 2] * TQ);
            int q3 = __float2int_rn(e[4 * kk + 3] * TQ);
            o[kk] = pack_q4(q0, q1, q2, q3);
        }
    }
}

// ---------------------------------------------------------------------------
// Kernel 1: int8 dp4a score GEMM + fused argmin.
// Per-row z scale s_r = 127/max|z_row| (deterministic); int32 accumulation is
// EXACT; per-thread 8 rows x 8 codes; top-2 32-bit keys; ambiguous rows
// (gap <= EPS_TIE) enqueued for exact fp32 rescore. Triple-buffered B. Occ 2.
// ---------------------------------------------------------------------------
__global__ __launch_bounds__(256, 2)
void argmin_kernel(const float* __restrict__ z) {
    __shared__ uint32_t A32[TM * PA];          // 8704 B
    __shared__ uint32_t B32[3][CH * PB];       // 30720 B
    __shared__ float    ens_s[K];              // 4096 B
    __shared__ float    srow_s[TM];            // z row scales
    __shared__ float    af_s[TM];              // -2/(s_r*TQ)
    __shared__ uint32_t red1[TM], red2[TM];

    const int tid = threadIdx.x;
    const int tx  = tid & 15;        // code lane: codes {tx + 16j}
    const int ty  = tid >> 4;        // row lane:  rows  {ty + 16i}

    const int n0  = blockIdx.x * TM;
    const int bB  = n0 >> 12;                     // 128 | 4096: no batch crossing
    const int hw0 = n0 & (HW - 1);
    const float* zb = z + (size_t)bB * CHW + hw0; // zb[k*HW + m]

    // Phase A: per-row exact zn (reference op order) + row max + scales.
    if (tid < TM) {
        float acc = 0.f, mx = 1e-20f;
        const float* p = zb + tid;
        #pragma unroll
        for (int c = 0; c < C; c++) {
            float v = p[c * HW];
            acc = __fadd_rn(acc, __fmul_rn(v, v));
            mx = fmaxf(mx, fabsf(v));
        }
        g_zn[n0 + tid] = acc;
        float s = 127.0f / mx;
        srow_s[tid] = s;
        af_s[tid]   = -2.0f / (s * TQ);
    }
    #pragma unroll
    for (int i = 0; i < 4; i++) ens_s[tid + 256 * i] = g_ens[tid + 256 * i];
    __syncthreads();    // srow/af ready

    // Phase B: quantize A tile (z re-reads are L1-hot from phase A).
    #pragma unroll
    for (int i = 0; i < 8; i++) {
        int f = tid + 256 * i;             // 2048 u32
        int row = f & 127, kk = f >> 7;    // kk 0..15
        float s = srow_s[row];
        int q0 = __float2int_rn(zb[(4 * kk + 0) * HW + row] * s);
        int q1 = __float2int_rn(zb[(4 * kk + 1) * HW + row] * s);
        int q2 = __float2int_rn(zb[(4 * kk + 2) * HW + row] * s);
        int q3 = __float2int_rn(zb[(4 * kk + 3) * HW + row] * s);
        A32[row * PA + kk] = pack_q4(q0, q1, q2, q3);
    }
    float af[8];
    #pragma unroll
    for (int i = 0; i < 8; i++) af[i] = af_s[ty + 16 * i];

    const uint32_t sbB = smem_u32(&B32[0][0]);
    // cp.async B chunk 0 into buffer 0 (8KB: 512 x 16B)
    {
        const char* src = (const char*)g_embq;
        #pragma unroll
        for (int i = 0; i < 2; i++) {
            int q = tid + 256 * i;                // 512 x 16B
            int code = q >> 2, seg = q & 3;
            uint32_t dst = sbB + (uint32_t)((code * PB + seg * 4) * 4);
            cp_async16(dst, src + q * 16);
        }
        asm volatile("cp.async.commit_group;\n");
    }

    uint32_t k1[8], k2[8];
    #pragma unroll
    for (int i = 0; i < 8; i++) { k1[i] = 0xFFFFFFFFu; k2[i] = 0xFFFFFFFFu; }

    for (int c = 0; c < NCH; c++) {
        if (c + 1 < NCH) {
            const char* src = (const char*)(g_embq + (c + 1) * CH * 16);
            const uint32_t boff = sbB + (uint32_t)(((c + 1) % 3) * CH * PB * 4);
            #pragma unroll
            for (int i = 0; i < 2; i++) {
                int q = tid + 256 * i;
                int code = q >> 2, seg = q & 3;
                cp_async16(boff + (uint32_t)((code * PB + seg * 4) * 4), src + q * 16);
            }
            asm volatile("cp.async.commit_group;\n");
            asm volatile("cp.async.wait_group 1;\n");
        } else {
            asm volatile("cp.async.wait_group 0;\n");
        }
        __syncthreads();   // chunk c visible; all threads past epi(c-1)

        const uint32_t* Bw = B32[c % 3];

        int acc[8][8];
        #pragma unroll
        for (int i = 0; i < 8; i++)
            #pragma unroll
            for (int j = 0; j < 8; j++) acc[i][j] = 0;

        #pragma unroll 4
        for (int kk = 0; kk < 16; kk++) {
            uint32_t a[8], b[8];
            #pragma unroll
            for (int i = 0; i < 8; i++) a[i] = A32[(ty + 16 * i) * PA + kk];
            #pragma unroll
            for (int j = 0; j < 8; j++) b[j] = Bw[(tx + 16 * j) * PB + kk];
            #pragma unroll
            for (int i = 0; i < 8; i++)
                #pragma unroll
                for (int j = 0; j < 8; j++)
                    acc[i][j] = __dp4a((int)a[i], (int)b[j], acc[i][j]);
        }

        // epilogue: exact I2F, row-scaled score, packed keys, top-2
        #pragma unroll
        for (int j = 0; j < 8; j++) {
            const int code = c * CH + tx + 16 * j;
            const float en = ens_s[code];
            #pragma unroll
            for (int i = 0; i < 8; i++) {
                float S   = (float)acc[i][j];
                float val = __fmaf_rn(af[i], S, en);
                uint32_t key = (__float_as_uint(val) & 0xFFFFF800u) | (uint32_t)code;
                uint32_t lo = umin(k1[i], key), hi = umax(k1[i], key);
                k1[i] = lo;
                k2[i] = umin(k2[i], hi);
            }
        }
        // no bottom sync: triple buffer guarantees no WAR on B
    }

    // reduce top-2 across the 16 tx lanes sharing each row (xor masks 1..8
    // stay within the 16-lane group)
    #pragma unroll
    for (int i = 0; i < 8; i++) {
        uint32_t a1 = k1[i], a2 = k2[i];
        #pragma unroll
        for (int m = 1; m <= 8; m <<= 1) {
            uint32_t o1 = __shfl_xor_sync(0xffffffffu, a1, m);
            uint32_t o2 = __shfl_xor_sync(0xffffffffu, a2, m);
            uint32_t lo = umin(a1, o1), hi = umax(a1, o1);
            a1 = lo;
            a2 = umin(umin(a2, o2), hi);
        }
        if (tx == 0) {
            red1[ty + 16 * i] = a1;
            red2[ty + 16 * i] = a2;
        }
    }
    __syncthreads();

    // per-row winner + ambiguity flagging
    if (tid < TM) {
        uint32_t t1 = red1[tid], t2 = red2[tid];
        g_idx[n0 + tid] = (int)(t1 & 0x7FFu);
        float v1f = __uint_as_float(t1 & 0xFFFFF800u);
        float v2f = __uint_as_float(t2 & 0xFFFFF800u);
        if (v2f - v1f <= EPS_TIE) {
            int pos = atomicAdd(&g_repair_count, 1);
            g_repair_rows[pos] = n0 + tid;
        }
    }
}

// ---------------------------------------------------------------------------
// Kernel 1b: exact full rescore of flagged rows (all 1024 codes), exact
// fp32 fmaf dot; min by lexicographic (d, code). (Unchanged; R9-proven.)
// ---------------------------------------------------------------------------
__global__ __launch_bounds__(256) void repair_kernel(const float* __restrict__ z,
                                                     const float* __restrict__ emb) {
    __shared__ float es[128 * 65];
    __shared__ float ze[16 * 66];
    __shared__ float zn_sh[16];
    __shared__ int   rows_sh[16];
    __shared__ int   s_base;

    const int tid = threadIdx.x;
    const int r   = tid >> 4;
    const int cc  = tid & 15;

    for (;;) {
        if (tid == 0) s_base = atomicAdd(&g_repair_tick, 16);
        __syncthreads();
        const int base = s_base;
        const int cnt  = g_repair_count;
        if (base >= cnt) break;
        const int nrows = min(16, cnt - base);

        if (tid < nrows) {
            int n = g_repair_rows[base + tid];
            rows_sh[tid] = n;
            zn_sh[tid]   = g_zn[n];
        }
        __syncthreads();
        #pragma unroll
        for (int i = 0; i < 4; i++) {
            int e2 = tid + 256 * i;
            int rr = e2 >> 6, k = e2 & 63;
            if (rr < nrows) {
                int n = rows_sh[rr], b = n >> 12, hw = n & (HW - 1);
                ze[rr * 66 + k] = z[(size_t)b * CHW + k * HW + hw];
            }
        }
        __syncthreads();

        ULL best = ~0ULL;
        for (int ch = 0; ch < 8; ch++) {
            #pragma unroll
            for (int i = 0; i < 32; i++) {
                int f = tid + 256 * i;
                int code = f >> 6, k = f & 63;
                es[code * 65 + k] = emb[ch * 8192 + f];
            }
            __syncthreads();
            if (r < nrows) {
                float S[8];
                #pragma unroll
                for (int j = 0; j < 8; j++) S[j] = 0.f;
                #pragma unroll 8
                for (int k = 0; k < 64; k++) {
                    float zk = ze[r * 66 + k];
                    #pragma unroll
                    for (int j = 0; j < 8; j++)
                        S[j] = __fmaf_rn(zk, es[(cc + 16 * j) * 65 + k], S[j]);
                }
                float zn = zn_sh[r];
                #pragma unroll
                for (int j = 0; j < 8; j++) {
                    int code = ch * 128 + cc + 16 * j;
                    float d = __fadd_rn(__fadd_rn(zn, __fmul_rn(-2.0f, S[j])), g_enorm[code]);
                    ULL key = ((ULL)__float_as_uint(d) << 32) | (unsigned)code;
                    if (key < best) best = key;
                }
            }
            __syncthreads();
        }
        #pragma unroll
        for (int m = 1; m < 16; m <<= 1) {
            ULL o = __shfl_xor_sync(0xffffffffu, best, m);
            best = u64min(best, o);
        }
        if (cc == 0 && r < nrows) g_idx[rows_sh[r]] = (int)(best & 0xffffffffULL);
        __syncthreads();
    }
}

// ---------------------------------------------------------------------------
// Kernel 2: gather + straight-through output + loss (fused last-block finish).
// 4 threads/row x 16 channels; e rows loaded as float4. (Unchanged; R11.)
// ---------------------------------------------------------------------------
__global__ __launch_bounds__(256) void gather_kernel(const float* __restrict__ z,
                                                     const float* __restrict__ emb,
                                                     float* __restrict__ out) {
    const int tid = threadIdx.x;
    const int m   = tid & 63;
    const int cg  = tid >> 6;
    const int n   = blockIdx.x * 64 + m;
    const int b   = n >> 12, hw = n & (HW - 1);
    const float* zp = z + (size_t)b * CHW + hw;
    float* op = out + (size_t)b * CHW + hw;
    const int idx = g_idx[n];
    const float4* e4 = (const float4*)(emb + idx * C + cg * 16);

    double s = 0.0;
    #pragma unroll
    for (int j = 0; j < 4; j++) {
        float4 q4 = __ldg(e4 + j);
        float qv[4] = {q4.x, q4.y, q4.z, q4.w};
        #pragma unroll
        for (int t = 0; t < 4; t++) {
            int c = cg * 16 + 4 * j + t;
            float zv   = zp[c * HW];
            float diff = __fadd_rn(qv[t], -zv);
            float qst  = __fadd_rn(zv, diff);
            op[c * HW] = qst;
            s += (double)__fmul_rn(diff, diff);
        }
    }

    __shared__ double sd[256];
    __shared__ bool s_last;
    sd[tid] = s;
    __syncthreads();
    for (int st = 128; st > 0; st >>= 1) {
        if (tid < st) sd[tid] += sd[tid + st];
        __syncthreads();
    }
    if (tid == 0) {
        g_partials[blockIdx.x] = sd[0];
        __threadfence();
        int t = atomicAdd(&g_gather_done, 1);
        s_last = (t == (int)gridDim.x - 1);
    }
    __syncthreads();

    if (s_last) {
        double s2 = 0.0;
        #pragma unroll
        for (int i = 0; i < 4; i++) s2 += g_partials[tid + 256 * i];
        sd[tid] = s2;
        __syncthreads();
        for (int st = 128; st > 0; st >>= 1) {
            if (tid < st) sd[tid] += sd[tid + st];
            __syncthreads();
        }
        if (tid == 0) {
            float mm = (float)(sd[0] / (double)((size_t)N * C));
            out[(size_t)N * C] = __fadd_rn(mm, 0.25f * mm);
        }
    }
}

// ---------------------------------------------------------------------------
extern "C" void kernel_launch(void* const* d_in, const int* in_sizes, int n_in,
                              void* d_out, int out_size) {
    const float* z   = (const float*)d_in[0];   // [16,64,64,64]
    const float* emb = (const float*)d_in[1];   // [1024,64]
    float* out = (float*)d_out;                 // 4194304 q_st + 1 loss

    prep_kernel  <<< 4, 256 >>>(emb);
    argmin_kernel<<< N / TM, 256 >>>(z);
    repair_kernel<<< 128, 256 >>>(z, emb);
    gather_kernel<<< N / 64, 256 >>>(z, emb, out);
}

// round 13
// speedup vs baseline: 1.4340x; 1.4340x over previous
#include <cuda_runtime.h>
#include <cuda_fp16.h>
#include <cstdint>

typedef unsigned long long ULL;

// Problem constants
constexpr int Bz = 16, C = 64, H = 64, W = 64;
constexpr int N  = Bz * H * W;     // 65536 rows
constexpr int K  = 1024;           // codes
constexpr int HW = H * W;          // 4096
constexpr int CHW = C * HW;        // 262144

// argmin tiling: 128 rows per CTA x 8 chunks of 128 codes
constexpr int TM  = 128;
constexpr int CH  = 128;
constexpr int NCH = K / CH;        // 8
constexpr int NBLK = N / TM;       // 512 argmin blocks

// smem layout (bytes). Operands half2 (u32), pitch 36 u32 (conflict-free frags).
constexpr int PW       = 36;
constexpr int A_BYTES  = TM * PW * 4;            // 18432
constexpr int B_OFF    = A_BYTES;                // 18432
constexpr int B_BYTES  = CH * PW * 4;            // 18432 per buffer (x3)
constexpr int ENS_OFF  = B_OFF + 3 * B_BYTES;    // 73728: biased norms [1024] f32
constexpr int ZF_OFF   = ENS_OFF + 4096;         // 77824: fp32 z tile [128][65]
constexpr int RED_OFF  = ZF_OFF + 33280;         // 111104: u32 red1[256], red2[256]
constexpr int WIN_OFF  = RED_OFF + 2048;         // 113152: int win[128]
constexpr int FLG_OFF  = WIN_OFF + 512;          // 113664: uchar flg[128]
constexpr int SMEM_BYTES = FLG_OFF + 128;        // 113792 (x2 CTAs = 227.6KB <= 228KB)

// Flag window: fp16 score noise (<=1.5e-4, ~21 sigma, proven R9/R11) + 32-bit
// key quantization (<=3.1e-5). Flagged rows get full exact-fp32 rescore.
constexpr float EPS_TIE = 1.81e-4f;
constexpr float VAL_BIAS = 0.1f;   // keeps val positive -> monotone float bits

// Device scratch (no allocations allowed)
__device__ float         g_enorm[K];            // exact ||e||^2 (reference rounding)
__device__ float         g_ens[K];              // VAL_BIAS + ||e||^2
__device__ uint32_t      g_embh[K * (C / 2)];   // half2-packed emb, [code][kpair]
__device__ float         g_zn[N];               // exact ||z||^2 (reference order)
__device__ unsigned char g_flag[N];             // ambiguity flags
__device__ int           g_done;
__device__ double        g_partials[NBLK];      // per-argmin-block clean-row sums
__device__ double        g_rpart[128];          // per-repair-block flagged-row sums

__device__ __forceinline__ uint32_t smem_u32(const void* p) {
    uint32_t a;
    asm("{ .reg .u64 t; cvta.to.shared.u64 t, %1; cvt.u32.u64 %0, t; }" : "=r"(a) : "l"(p));
    return a;
}
__device__ __forceinline__ void cp_async16(uint32_t dst, const void* src) {
    asm volatile("cp.async.cg.shared.global [%0], [%1], 16;\n" :: "r"(dst), "l"(src));
}
__device__ __forceinline__ void mma16(float* d,
                                      uint32_t a0, uint32_t a1, uint32_t a2, uint32_t a3,
                                      uint32_t b0, uint32_t b1) {
    asm volatile("mma.sync.aligned.m16n8k16.row.col.f32.f16.f16.f32 "
                 "{%0,%1,%2,%3}, {%4,%5,%6,%7}, {%8,%9}, {%0,%1,%2,%3};"
                 : "+f"(d[0]), "+f"(d[1]), "+f"(d[2]), "+f"(d[3])
                 : "r"(a0), "r"(a1), "r"(a2), "r"(a3), "r"(b0), "r"(b1));
}
__device__ __forceinline__ ULL u64min(ULL a, ULL b) { return a < b ? a : b; }
__device__ __forceinline__ uint32_t pack_h2(float x, float y) {
    __half2 h = __floats2half2_rn(x, y);
    return *(uint32_t*)&h;
}

// ---------------------------------------------------------------------------
// Kernel 0: ||e||^2 (reference rounding), biased norms, half2 emb, counters.
// ---------------------------------------------------------------------------
__global__ void prep_kernel(const float* __restrict__ emb) {
    if (blockIdx.x == 0 && threadIdx.x == 0) g_done = 0;
    int code = blockIdx.x * blockDim.x + threadIdx.x;   // 0..1023
    if (code < K) {
        const float* e = emb + code * C;
        uint32_t* o = g_embh + code * (C / 2);
        float acc = 0.f;
        #pragma unroll
        for (int c = 0; c < C; c++) {
            float v = e[c];
            acc = __fadd_rn(acc, __fmul_rn(v, v));
        }
        #pragma unroll
        for (int kp = 0; kp < C / 2; kp++)
            o[kp] = pack_h2(e[2 * kp], e[2 * kp + 1]);
        g_enorm[code] = acc;
        g_ens[code]   = VAL_BIAS + acc;
    }
}

// ---------------------------------------------------------------------------
// Kernel 1: fp16 mma score GEMM + fused argmin + fused gather for clean rows.
// R11-proven core. Tail: per-row winner/flag, then q_st + loss partial for
// non-flagged rows straight from the smem z tile. Flagged rows -> g_flag.
// ---------------------------------------------------------------------------
__global__ __launch_bounds__(256, 2)
void argmin_kernel(const float* __restrict__ z,
                   const float* __restrict__ embf,
                   float* __restrict__ out) {
    extern __shared__ char smem[];
    uint32_t*      A2    = (uint32_t*)smem;                 // [128][36] half2
    uint32_t*      B2    = (uint32_t*)(smem + B_OFF);       // [3][128][36]
    float*         ens_s = (float*)(smem + ENS_OFF);        // [1024]
    float*         zf    = (float*)(smem + ZF_OFF);         // [128][65] fp32 z
    uint32_t*      red1  = (uint32_t*)(smem + RED_OFF);     // [2][128]
    uint32_t*      red2  = red1 + 256;                      // [2][128]
    int*           winsh = (int*)(smem + WIN_OFF);          // [128]
    unsigned char* flgsh = (unsigned char*)(smem + FLG_OFF);// [128]
    const uint32_t sb = smem_u32(smem);

    const int tid  = threadIdx.x;
    const int lane = tid & 31;
    const int wid  = tid >> 5;
    const int wm   = wid & 3;       // row band (32 rows)
    const int wn   = wid >> 2;      // code half (64 codes)
    const int arow = lane >> 2;     // 0..7
    const int acol = lane & 3;      // 0..3

    const int n0  = blockIdx.x * TM;
    const int bB  = n0 >> 12;                     // 128 | 4096: no batch crossing
    const int hw0 = n0 & (HW - 1);
    const float* zb = z + (size_t)bB * CHW + hw0; // zb[k*HW + m]

    // --- cp.async B chunk 0 first (independent of A) ---
    {
        const char* src = (const char*)g_embh;
        #pragma unroll
        for (int i = 0; i < 4; i++) {
            int q = tid + 256 * i;                // 1024 x 16B
            int code = q >> 3, seg = q & 7;
            uint32_t dst = sb + (uint32_t)(B_OFF + code * (PW * 4) + seg * 16);
            cp_async16(dst, src + q * 16);
        }
        asm volatile("cp.async.commit_group;\n");
    }

    // --- A tile: z -> half2 pairs A2[m][kp] AND fp32 copy into zf[m][c] ---
    #pragma unroll
    for (int i = 0; i < 16; i++) {
        int f  = tid + 256 * i;                   // 4096 (kp, m) pairs
        int m  = f & 127, kp = f >> 7;
        float v0 = zb[(2 * kp) * HW + m];
        float v1 = zb[(2 * kp + 1) * HW + m];
        A2[m * PW + kp] = pack_h2(v0, v1);
        zf[m * 65 + 2 * kp]     = v0;
        zf[m * 65 + 2 * kp + 1] = v1;
    }
    // exact ||z||^2 per row (reference op order) -> global, for repair only.
    if (tid < TM) {
        float acc = 0.f;
        const float* p = zb + tid;
        #pragma unroll
        for (int c = 0; c < C; c++) {
            float v = p[c * HW];
            acc = __fadd_rn(acc, __fmul_rn(v, v));
        }
        g_zn[n0 + tid] = acc;
    }
    #pragma unroll
    for (int i = 0; i < 4; i++) ens_s[tid + 256 * i] = g_ens[tid + 256 * i];

    // per-thread top-2 32-bit keys per (mi, rh)
    uint32_t k1[2][2], k2[2][2];
    #pragma unroll
    for (int a = 0; a < 2; a++)
        #pragma unroll
        for (int b = 0; b < 2; b++) { k1[a][b] = 0xFFFFFFFFu; k2[a][b] = 0xFFFFFFFFu; }

    for (int c = 0; c < NCH; c++) {
        // prefetch chunk c+1 into buf[(c+1)%3]; its last reader was iter c-2.
        if (c + 1 < NCH) {
            const char* src = (const char*)(g_embh + (c + 1) * CH * (C / 2));
            const int boff = B_OFF + ((c + 1) % 3) * B_BYTES;
            #pragma unroll
            for (int i = 0; i < 4; i++) {
                int q = tid + 256 * i;
                int code = q >> 3, seg = q & 7;
                uint32_t dst = sb + (uint32_t)(boff + code * (PW * 4) + seg * 16);
                cp_async16(dst, src + q * 16);
            }
            asm volatile("cp.async.commit_group;\n");
            asm volatile("cp.async.wait_group 1;\n");
        } else {
            asm volatile("cp.async.wait_group 0;\n");
        }
        __syncthreads();   // chunk c visible; all threads past epi(c-1)

        const uint32_t* Aw = A2 + (32 * wm) * PW;
        const uint32_t* Bw = B2 + (c % 3) * (CH * PW) + (64 * wn) * PW;

        float acc[2][8][4];
        #pragma unroll
        for (int mi = 0; mi < 2; mi++)
            #pragma unroll
            for (int ni = 0; ni < 8; ni++)
                #pragma unroll
                for (int r = 0; r < 4; r++) acc[mi][ni][r] = 0.f;

        #pragma unroll
        for (int ks = 0; ks < 4; ks++) {          // 4 k-steps of 16
            uint32_t af[2][4];
            #pragma unroll
            for (int mi = 0; mi < 2; mi++) {
                const uint32_t* Ap = Aw + (16 * mi + arow) * PW + ks * 8 + acol;
                af[mi][0] = Ap[0];
                af[mi][1] = Ap[8 * PW];
                af[mi][2] = Ap[4];
                af[mi][3] = Ap[8 * PW + 4];
            }
            uint32_t bf[8][2];
            #pragma unroll
            for (int ni = 0; ni < 8; ni++) {
                const uint32_t* Bp = Bw + (8 * ni + arow) * PW + ks * 8 + acol;
                bf[ni][0] = Bp[0];
                bf[ni][1] = Bp[4];
            }
            #pragma unroll
            for (int mi = 0; mi < 2; mi++)
                #pragma unroll
                for (int ni = 0; ni < 8; ni++)
                    mma16(acc[mi][ni],
                          af[mi][0], af[mi][1], af[mi][2], af[mi][3],
                          bf[ni][0], bf[ni][1]);
        }

        // epilogue: biased scores -> packed 32-bit keys -> per-thread top-2
        const int code0 = c * CH + 64 * wn;
        #pragma unroll
        for (int ni = 0; ni < 8; ni++) {
            float2 ens2 = *(const float2*)(ens_s + code0 + 8 * ni + 2 * acol);
            const uint32_t cbase = (uint32_t)(code0 + 8 * ni + 2 * acol);
            #pragma unroll
            for (int mi = 0; mi < 2; mi++)
                #pragma unroll
                for (int rh = 0; rh < 2; rh++) {
                    float v0 = __fmaf_rn(-2.0f, acc[mi][ni][2 * rh + 0], ens2.x);
                    float v1 = __fmaf_rn(-2.0f, acc[mi][ni][2 * rh + 1], ens2.y);
                    uint32_t key0 = (__float_as_uint(v0) & 0xFFFFF800u) | cbase;
                    uint32_t key1 = (__float_as_uint(v1) & 0xFFFFF800u) | (cbase + 1);
                    uint32_t lo, hi;
                    lo = umin(k1[mi][rh], key0); hi = umax(k1[mi][rh], key0);
                    k1[mi][rh] = lo; k2[mi][rh] = umin(k2[mi][rh], hi);
                    lo = umin(k1[mi][rh], key1); hi = umax(k1[mi][rh], key1);
                    k1[mi][rh] = lo; k2[mi][rh] = umin(k2[mi][rh], hi);
                }
        }
        // no bottom sync: triple buffer guarantees no WAR on B
    }

    // reduce top-2 across the 4 acol lanes sharing each row
    #pragma unroll
    for (int mi = 0; mi < 2; mi++)
        #pragma unroll
        for (int rh = 0; rh < 2; rh++) {
            uint32_t a1 = k1[mi][rh], a2 = k2[mi][rh];
            #pragma unroll
            for (int m = 1; m <= 2; m <<= 1) {
                uint32_t o1 = __shfl_xor_sync(0xffffffffu, a1, m);
                uint32_t o2 = __shfl_xor_sync(0xffffffffu, a2, m);
                uint32_t lo = umin(a1, o1), hi = umax(a1, o1);
                a1 = lo;
                a2 = umin(umin(a2, o2), hi);
            }
            if (acol == 0) {
                int row = 32 * wm + 16 * mi + arow + 8 * rh;
                red1[wn * TM + row] = a1;
                red2[wn * TM + row] = a2;
            }
        }
    __syncthreads();

    // per-row winner across code-halves + ambiguity flagging
    if (tid < TM) {
        uint32_t a1 = red1[tid], b1 = red1[TM + tid];
        uint32_t a2 = red2[tid], b2 = red2[TM + tid];
        uint32_t t1 = umin(a1, b1);
        uint32_t hi = umax(a1, b1);
        uint32_t t2 = umin(umin(a2, b2), hi);
        winsh[tid] = (int)(t1 & 0x7FFu);
        float v1f = __uint_as_float(t1 & 0xFFFFF800u);
        float v2f = __uint_as_float(t2 & 0xFFFFF800u);
        int fl = (v2f - v1f <= EPS_TIE) ? 1 : 0;
        flgsh[tid] = (unsigned char)fl;
        g_flag[n0 + tid] = (unsigned char)fl;
    }
    __syncthreads();

    // fused gather + q_st + loss partial for NON-flagged rows (z from smem)
    double s = 0.0;
    const int cg = tid >> 6;                      // channel group 0..3
    #pragma unroll
    for (int it = 0; it < 2; it++) {
        int m = (tid & 63) + 64 * it;
        if (!flgsh[m]) {
            int idx = winsh[m];
            const float4* e4 = (const float4*)(embf + idx * C + cg * 16);
            float* op = out + (size_t)bB * CHW + hw0 + m;
            const float* zr = zf + m * 65 + cg * 16;
            #pragma unroll
            for (int j = 0; j < 4; j++) {
                float4 q4 = __ldg(e4 + j);
                float qv[4] = {q4.x, q4.y, q4.z, q4.w};
                #pragma unroll
                for (int t = 0; t < 4; t++) {
                    int c = cg * 16 + 4 * j + t;
                    float zv   = zr[4 * j + t];
                    float diff = __fadd_rn(qv[t], -zv);
                    float qst  = __fadd_rn(zv, diff);
                    op[(size_t)c * HW] = qst;
                    s += (double)__fmul_rn(diff, diff);
                }
            }
        }
    }
    // block partial (fixed tree, reuse A2 region as double scratch)
    double* sd = (double*)smem;
    __syncthreads();
    sd[tid] = s;
    __syncthreads();
    for (int st = 128; st > 0; st >>= 1) {
        if (tid < st) sd[tid] += sd[tid + st];
        __syncthreads();
    }
    if (tid == 0) g_partials[blockIdx.x] = sd[0];
}

// ---------------------------------------------------------------------------
// Kernel 2: repair flagged rows end-to-end. 128 blocks x 512-row regions.
// Ordered ballot compaction of g_flag; exact fp32 rescore (R9-proven);
// q_st writes + per-row d^2 into POSITIONAL slots -> deterministic partial.
// Last block sums all partials (fixed order) -> loss.
// ---------------------------------------------------------------------------
__global__ __launch_bounds__(256) void repair_kernel(const float* __restrict__ z,
                                                     const float* __restrict__ emb,
                                                     float* __restrict__ out) {
    __shared__ float  es[128 * 65];    // 33280
    __shared__ float  ze[16 * 66];
    __shared__ float  zn_sh[16];
    __shared__ int    rows_sh[16];
    __shared__ int    list[512];
    __shared__ int    cnts[16], offs[16], cnt;
    __shared__ double ds[512];
    __shared__ bool   s_last;

    const int tid = threadIdx.x;
    const int r   = tid >> 4;
    const int cc  = tid & 15;
    const int wdc = tid >> 5;          // warp 0..7
    const int ln  = tid & 31;
    const int base = blockIdx.x * 512;

    // zero positional slots
    ds[tid] = 0.0; ds[tid + 256] = 0.0;

    // ordered compaction of flagged rows in [base, base+512)
    int cflag[2];
    #pragma unroll
    for (int s = 0; s < 2; s++) {
        int rr = base + wdc * 64 + s * 32 + ln;
        cflag[s] = g_flag[rr];
        unsigned mk = __ballot_sync(0xffffffffu, cflag[s]);
        if (ln == 0) cnts[wdc * 2 + s] = __popc(mk);
    }
    __syncthreads();
    if (tid == 0) {
        int acc = 0;
        for (int i = 0; i < 16; i++) { offs[i] = acc; acc += cnts[i]; }
        cnt = acc;
    }
    __syncthreads();
    #pragma unroll
    for (int s = 0; s < 2; s++) {
        unsigned mk = __ballot_sync(0xffffffffu, cflag[s]);
        if (cflag[s]) {
            int pos = offs[wdc * 2 + s] + __popc(mk & ((1u << ln) - 1u));
            list[pos] = base + wdc * 64 + s * 32 + ln;
        }
    }
    __syncthreads();

    for (int b0 = 0; b0 < cnt; b0 += 16) {
        const int nrows = min(16, cnt - b0);
        if (tid < nrows) {
            int n = list[b0 + tid];
            rows_sh[tid] = n;
            zn_sh[tid]   = g_zn[n];
        }
        __syncthreads();
        #pragma unroll
        for (int i = 0; i < 4; i++) {
            int e2 = tid + 256 * i;
            int rr = e2 >> 6, k = e2 & 63;
            if (rr < nrows) {
                int n = rows_sh[rr], b = n >> 12, hw = n & (HW - 1);
                ze[rr * 66 + k] = z[(size_t)b * CHW + k * HW + hw];
            }
        }
        __syncthreads();

        ULL best = ~0ULL;
        for (int ch = 0; ch < 8; ch++) {
            #pragma unroll
            for (int i = 0; i < 32; i++) {
                int f = tid + 256 * i;
                int code = f >> 6, k = f & 63;
                es[code * 65 + k] = emb[ch * 8192 + f];
            }
            __syncthreads();
            if (r < nrows) {
                float S[8];
                #pragma unroll
                for (int j = 0; j < 8; j++) S[j] = 0.f;
                #pragma unroll 8
                for (int k = 0; k < 64; k++) {
                    float zk = ze[r * 66 + k];
                    #pragma unroll
                    for (int j = 0; j < 8; j++)
                        S[j] = __fmaf_rn(zk, es[(cc + 16 * j) * 65 + k], S[j]);
                }
                float zn = zn_sh[r];
                #pragma unroll
                for (int j = 0; j < 8; j++) {
                    int code = ch * 128 + cc + 16 * j;
                    float d = __fadd_rn(__fadd_rn(zn, __fmul_rn(-2.0f, S[j])), g_enorm[code]);
                    ULL key = ((ULL)__float_as_uint(d) << 32) | (unsigned)code;
                    if (key < best) best = key;
                }
            }
            __syncthreads();
        }
        #pragma unroll
        for (int m = 1; m < 16; m <<= 1) {
            ULL o = __shfl_xor_sync(0xffffffffu, best, m);
            best = u64min(best, o);
        }
        // all 16 lanes of a row-group now hold the winner: gather + q_st + d2
        double sloc = 0.0;
        if (r < nrows) {
            int code = (int)(best & 0xffffffffULL);
            int n = rows_sh[r];
            int b = n >> 12, hw = n & (HW - 1);
            float* op = out + (size_t)b * CHW + hw;
            const float* e = emb + code * C;
            #pragma unroll
            for (int t = 0; t < 4; t++) {
                int c = 4 * cc + t;
                float zv   = ze[r * 66 + c];
                float q    = __ldg(e + c);
                float diff = __fadd_rn(q, -zv);
                float qst  = __fadd_rn(zv, diff);
                op[(size_t)c * HW] = qst;
                sloc += (double)__fmul_rn(diff, diff);
            }
        }
        #pragma unroll
        for (int m = 1; m < 16; m <<= 1)
            sloc += __shfl_xor_sync(0xffffffffu, sloc, m);
        if (cc == 0 && r < nrows) ds[b0 + r] = sloc;
        __syncthreads();
    }

    // deterministic block partial over positional slots
    ds[tid] += ds[tid + 256];
    __syncthreads();
    for (int st = 128; st > 0; st >>= 1) {
        if (tid < st) ds[tid] += ds[tid + st];
        __syncthreads();
    }
    if (tid == 0) {
        g_rpart[blockIdx.x] = ds[0];
        __threadfence();
        int t = atomicAdd(&g_done, 1);
        s_last = (t == 127);
    }
    __syncthreads();

    // last block: fixed-order final sum -> loss
    if (s_last) {
        double s3 = g_partials[tid] + g_partials[tid + 256];
        if (tid < 128) s3 += g_rpart[tid];
        ds[tid] = s3;
        __syncthreads();
        for (int st = 128; st > 0; st >>= 1) {
            if (tid < st) ds[tid] += ds[tid + st];
            __syncthreads();
        }
        if (tid == 0) {
            float mm = (float)(ds[0] / (double)((size_t)N * C));
            out[(size_t)N * C] = __fadd_rn(mm, 0.25f * mm);
        }
    }
}

// ---------------------------------------------------------------------------
extern "C" void kernel_launch(void* const* d_in, const int* in_sizes, int n_in,
                              void* d_out, int out_size) {
    const float* z   = (const float*)d_in[0];   // [16,64,64,64]
    const float* emb = (const float*)d_in[1];   // [1024,64]
    float* out = (float*)d_out;                 // 4194304 q_st + 1 loss

    cudaFuncSetAttribute(argmin_kernel,
                         cudaFuncAttributeMaxDynamicSharedMemorySize, SMEM_BYTES);

    prep_kernel  <<< 4, 256 >>>(emb);
    argmin_kernel<<< NBLK, 256, SMEM_BYTES >>>(z, emb, out);
    repair_kernel<<< 128, 256 >>>(z, emb, out);
}

// round 15
// speedup vs baseline: 1.8228x; 1.2712x over previous
#include <cuda_runtime.h>
#include <cuda_fp16.h>
#include <cstdint>

typedef unsigned long long ULL;

// Problem constants
constexpr int Bz = 16, C = 64, H = 64, W = 64;
constexpr int N  = Bz * H * W;     // 65536 rows
constexpr int K  = 1024;           // codes
constexpr int HW = H * W;          // 4096
constexpr int CHW = C * HW;        // 262144

// argmin tiling: 128 rows per CTA x 8 chunks of 128 codes
constexpr int TM  = 128;
constexpr int CH  = 128;
constexpr int NCH = K / CH;        // 8

// smem layout (bytes). Operands half2 (u32), pitch 36 u32 (conflict-free frags).
constexpr int PW       = 36;
constexpr int A_BYTES  = TM * PW * 4;            // 18432
constexpr int B_OFF    = A_BYTES;                // 18432
constexpr int B_BYTES  = CH * PW * 4;            // 18432 per buffer (x3)
constexpr int ENS_OFF  = B_OFF + 3 * B_BYTES;    // 73728: biased norms [1024] f32
constexpr int RED_OFF  = ENS_OFF + 4096;         // 77824: u32 red1[256], red2[256]
constexpr int SMEM_BYTES = RED_OFF + 2048;       // 79872  (occ 2 with big margin)

// Flag window: fp16 score noise (<=1.5e-4, ~21 sigma, proven R9/R11) + 32-bit
// key quantization (<=3.1e-5). Flagged rows get full exact-fp32 rescore.
constexpr float EPS_TIE = 1.81e-4f;
constexpr float VAL_BIAS = 0.1f;   // keeps val positive -> monotone float bits

// Device scratch (no allocations allowed)
__device__ int      g_idx[N];
__device__ float    g_enorm[K];            // exact ||e||^2 (reference rounding)
__device__ float    g_ens[K];              // VAL_BIAS + ||e||^2
__device__ uint32_t g_embh[K * (C / 2)];   // half2-packed emb, [code][kpair]
__device__ float    g_zn[N];               // exact ||z||^2 (reference order)
__device__ int      g_repair_rows[N];
__device__ int      g_repair_count;
__device__ int      g_repair_tick;
__device__ int      g_gather_done;
__device__ double   g_partials[1024];

__device__ __forceinline__ uint32_t smem_u32(const void* p) {
    uint32_t a;
    asm("{ .reg .u64 t; cvta.to.shared.u64 t, %1; cvt.u32.u64 %0, t; }" : "=r"(a) : "l"(p));
    return a;
}
__device__ __forceinline__ void cp_async16(uint32_t dst, const void* src) {
    asm volatile("cp.async.cg.shared.global [%0], [%1], 16;\n" :: "r"(dst), "l"(src));
}
__device__ __forceinline__ void mma16(float* d,
                                      uint32_t a0, uint32_t a1, uint32_t a2, uint32_t a3,
                                      uint32_t b0, uint32_t b1) {
    asm volatile("mma.sync.aligned.m16n8k16.row.col.f32.f16.f16.f32 "
                 "{%0,%1,%2,%3}, {%4,%5,%6,%7}, {%8,%9}, {%0,%1,%2,%3};"
                 : "+f"(d[0]), "+f"(d[1]), "+f"(d[2]), "+f"(d[3])
                 : "r"(a0), "r"(a1), "r"(a2), "r"(a3), "r"(b0), "r"(b1));
}
__device__ __forceinline__ ULL u64min(ULL a, ULL b) { return a < b ? a : b; }
__device__ __forceinline__ uint32_t pack_h2(float x, float y) {
    __half2 h = __floats2half2_rn(x, y);
    return *(uint32_t*)&h;
}

// ---------------------------------------------------------------------------
// Kernel 0: parallel prep. 128 blocks x 256 threads; 32 threads per code do
// the loads + half2 packing; ONE thread per code replays the sequential
// reference-order norm from smem (bit-identical to the serial version).
// ---------------------------------------------------------------------------
__global__ __launch_bounds__(256) void prep_kernel(const float* __restrict__ emb) {
    __shared__ float ec[8][64];
    if (blockIdx.x == 0 && threadIdx.x == 0) {
        g_repair_count = 0; g_repair_tick = 0; g_gather_done = 0;
    }
    const int tid = threadIdx.x;
    const int cl  = tid >> 5;           // code slot 0..7
    const int t   = tid & 31;           // lane within code
    const int code = blockIdx.x * 8 + cl;   // 128 blocks x 8 = 1024 codes

    const float2 v = *(const float2*)(emb + code * C + 2 * t);
    ec[cl][2 * t]     = v.x;
    ec[cl][2 * t + 1] = v.y;
    g_embh[code * (C / 2) + t] = pack_h2(v.x, v.y);
    __syncthreads();

    if (t == 0) {
        float acc = 0.f;
        #pragma unroll
        for (int c = 0; c < C; c++) {
            float e = ec[cl][c];
            acc = __fadd_rn(acc, __fmul_rn(e, e));   // reference op order
        }
        g_enorm[code] = acc;
        g_ens[code]   = VAL_BIAS + acc;
    }
}

// ---------------------------------------------------------------------------
// Kernel 1: single-pass fp16 mma score GEMM + fused argmin. (R11, unchanged.)
// Score key: val = fma(-2, S, 0.1+en), packed (valbits & ~0x7FF) | code.
// Top-2 per thread; ambiguous rows enqueued. Triple-buffered B. Occ 2.
// ---------------------------------------------------------------------------
__global__ __launch_bounds__(256, 2)
void argmin_kernel(const float* __restrict__ z) {
    extern __shared__ char smem[];
    uint32_t* A2    = (uint32_t*)smem;                 // [128][36] half2
    uint32_t* B2    = (uint32_t*)(smem + B_OFF);       // [3][128][36]
    float*    ens_s = (float*)(smem + ENS_OFF);        // [1024] biased norms
    uint32_t* red1  = (uint32_t*)(smem + RED_OFF);     // [2][128] best key
    uint32_t* red2  = red1 + 256;                      // [2][128] 2nd key
    const uint32_t sb = smem_u32(smem);

    const int tid  = threadIdx.x;
    const int lane = tid & 31;
    const int wid  = tid >> 5;
    const int wm   = wid & 3;       // row band (32 rows)
    const int wn   = wid >> 2;      // code half (64 codes)
    const int arow = lane >> 2;     // 0..7
    const int acol = lane & 3;      // 0..3

    const int n0  = blockIdx.x * TM;
    const int bB  = n0 >> 12;                     // 128 | 4096: no batch crossing
    const int hw0 = n0 & (HW - 1);
    const float* zb = z + (size_t)bB * CHW + hw0; // zb[k*HW + m]

    // --- A tile: z -> half2 pairs A2[m][kp]; full 128 rows x 32 kp ---
    #pragma unroll
    for (int i = 0; i < 16; i++) {
        int f  = tid + 256 * i;                   // 4096 (kp, m) pairs
        int m  = f & 127, kp = f >> 7;
        float v0 = zb[(2 * kp) * HW + m];
        float v1 = zb[(2 * kp + 1) * HW + m];
        A2[m * PW + kp] = pack_h2(v0, v1);
    }
    // exact ||z||^2 per row (reference op order) -> global, for repair only.
    if (tid < TM) {
        float acc = 0.f;
        const float* p = zb + tid;
        #pragma unroll
        for (int c = 0; c < C; c++) {
            float v = p[c * HW];
            acc = __fadd_rn(acc, __fmul_rn(v, v));
        }
        g_zn[n0 + tid] = acc;
    }
    #pragma unroll
    for (int i = 0; i < 4; i++) ens_s[tid + 256 * i] = g_ens[tid + 256 * i];

    // --- cp.async B chunk 0 into buffer 0 ---
    {
        const char* src = (const char*)g_embh;
        #pragma unroll
        for (int i = 0; i < 4; i++) {
            int q = tid + 256 * i;                // 1024 x 16B
            int code = q >> 3, seg = q & 7;
            uint32_t dst = sb + (uint32_t)(B_OFF + code * (PW * 4) + seg * 16);
            cp_async16(dst, src + q * 16);
        }
        asm volatile("cp.async.commit_group;\n");
    }

    // per-thread top-2 32-bit keys per (mi, rh)
    uint32_t k1[2][2], k2[2][2];
    #pragma unroll
    for (int a = 0; a < 2; a++)
        #pragma unroll
        for (int b = 0; b < 2; b++) { k1[a][b] = 0xFFFFFFFFu; k2[a][b] = 0xFFFFFFFFu; }

    for (int c = 0; c < NCH; c++) {
        // prefetch chunk c+1 into buf[(c+1)%3]; its last reader was iter c-2,
        // finished before sync(c-1) which we already passed.
        if (c + 1 < NCH) {
            const char* src = (const char*)(g_embh + (c + 1) * CH * (C / 2));
            const int boff = B_OFF + ((c + 1) % 3) * B_BYTES;
            #pragma unroll
            for (int i = 0; i < 4; i++) {
                int q = tid + 256 * i;
                int code = q >> 3, seg = q & 7;
                uint32_t dst = sb + (uint32_t)(boff + code * (PW * 4) + seg * 16);
                cp_async16(dst, src + q * 16);
            }
            asm volatile("cp.async.commit_group;\n");
            asm volatile("cp.async.wait_group 1;\n");
        } else {
            asm volatile("cp.async.wait_group 0;\n");
        }
        __syncthreads();   // chunk c data visible; all warps past epi(c-1)

        const uint32_t* Aw = A2 + (32 * wm) * PW;
        const uint32_t* Bw = B2 + (c % 3) * (CH * PW) + (64 * wn) * PW;

        float acc[2][8][4];
        #pragma unroll
        for (int mi = 0; mi < 2; mi++)
            #pragma unroll
            for (int ni = 0; ni < 8; ni++)
                #pragma unroll
                for (int r = 0; r < 4; r++) acc[mi][ni][r] = 0.f;

        #pragma unroll
        for (int ks = 0; ks < 4; ks++) {          // 4 k-steps of 16
            uint32_t af[2][4];
            #pragma unroll
            for (int mi = 0; mi < 2; mi++) {
                const uint32_t* Ap = Aw + (16 * mi + arow) * PW + ks * 8 + acol;
                af[mi][0] = Ap[0];
                af[mi][1] = Ap[8 * PW];
                af[mi][2] = Ap[4];
                af[mi][3] = Ap[8 * PW + 4];
            }
            uint32_t bf[8][2];
            #pragma unroll
            for (int ni = 0; ni < 8; ni++) {
                const uint32_t* Bp = Bw + (8 * ni + arow) * PW + ks * 8 + acol;
                bf[ni][0] = Bp[0];
                bf[ni][1] = Bp[4];
            }
            #pragma unroll
            for (int mi = 0; mi < 2; mi++)
                #pragma unroll
                for (int ni = 0; ni < 8; ni++)
                    mma16(acc[mi][ni],
                          af[mi][0], af[mi][1], af[mi][2], af[mi][3],
                          bf[ni][0], bf[ni][1]);
        }

        // epilogue: biased scores -> packed 32-bit keys -> per-thread top-2
        const int code0 = c * CH + 64 * wn;
        #pragma unroll
        for (int ni = 0; ni < 8; ni++) {
            float2 ens2 = *(const float2*)(ens_s + code0 + 8 * ni + 2 * acol);
            const uint32_t cbase = (uint32_t)(code0 + 8 * ni + 2 * acol);
            #pragma unroll
            for (int mi = 0; mi < 2; mi++)
                #pragma unroll
                for (int rh = 0; rh < 2; rh++) {
                    float v0 = __fmaf_rn(-2.0f, acc[mi][ni][2 * rh + 0], ens2.x);
                    float v1 = __fmaf_rn(-2.0f, acc[mi][ni][2 * rh + 1], ens2.y);
                    uint32_t key0 = (__float_as_uint(v0) & 0xFFFFF800u) | cbase;
                    uint32_t key1 = (__float_as_uint(v1) & 0xFFFFF800u) | (cbase + 1);
                    uint32_t lo, hi;
                    lo = umin(k1[mi][rh], key0); hi = umax(k1[mi][rh], key0);
                    k1[mi][rh] = lo; k2[mi][rh] = umin(k2[mi][rh], hi);
                    lo = umin(k1[mi][rh], key1); hi = umax(k1[mi][rh], key1);
                    k1[mi][rh] = lo; k2[mi][rh] = umin(k2[mi][rh], hi);
                }
        }
        // no bottom sync: triple buffer guarantees no WAR on B
    }

    // reduce top-2 across the 4 acol lanes sharing each row
    #pragma unroll
    for (int mi = 0; mi < 2; mi++)
        #pragma unroll
        for (int rh = 0; rh < 2; rh++) {
            uint32_t a1 = k1[mi][rh], a2 = k2[mi][rh];
            #pragma unroll
            for (int m = 1; m <= 2; m <<= 1) {
                uint32_t o1 = __shfl_xor_sync(0xffffffffu, a1, m);
                uint32_t o2 = __shfl_xor_sync(0xffffffffu, a2, m);
                uint32_t lo = umin(a1, o1), hi = umax(a1, o1);
                a1 = lo;
                a2 = umin(umin(a2, o2), hi);
            }
            if (acol == 0) {
                int row = 32 * wm + 16 * mi + arow + 8 * rh;
                red1[wn * TM + row] = a1;
                red2[wn * TM + row] = a2;
            }
        }
    __syncthreads();

    // final per-row merge across the two code-halves + ambiguity flagging
    if (tid < TM) {
        uint32_t a1 = red1[tid], b1 = red1[TM + tid];
        uint32_t a2 = red2[tid], b2 = red2[TM + tid];
        uint32_t t1 = umin(a1, b1);
        uint32_t hi = umax(a1, b1);
        uint32_t t2 = umin(umin(a2, b2), hi);

        g_idx[n0 + tid] = (int)(t1 & 0x7FFu);     // provisional winner
        float v1f = __uint_as_float(t1 & 0xFFFFF800u);
        float v2f = __uint_as_float(t2 & 0xFFFFF800u);
        if (v2f - v1f <= EPS_TIE) {
            int pos = atomicAdd(&g_repair_count, 1);
            g_repair_rows[pos] = n0 + tid;
        }
    }
}

// ---------------------------------------------------------------------------
// Kernel 1b: exact full rescore of flagged rows (all 1024 codes), exact
// fp32 fmaf dot; min by lexicographic (d, code). (Unchanged; R9-proven.)
// ---------------------------------------------------------------------------
__global__ __launch_bounds__(256) void repair_kernel(const float* __restrict__ z,
                                                     const float* __restrict__ emb) {
    __shared__ float es[128 * 65];
    __shared__ float ze[16 * 66];
    __shared__ float zn_sh[16];
    __shared__ int   rows_sh[16];
    __shared__ int   s_base;

    const int tid = threadIdx.x;
    const int r   = tid >> 4;
    const int cc  = tid & 15;

    for (;;) {
        if (tid == 0) s_base = atomicAdd(&g_repair_tick, 16);
        __syncthreads();
        const int base = s_base;
        const int cnt  = g_repair_count;
        if (base >= cnt) break;
        const int nrows = min(16, cnt - base);

        if (tid < nrows) {
            int n = g_repair_rows[base + tid];
            rows_sh[tid] = n;
            zn_sh[tid]   = g_zn[n];
        }
        __syncthreads();
        #pragma unroll
        for (int i = 0; i < 4; i++) {
            int e2 = tid + 256 * i;
            int rr = e2 >> 6, k = e2 & 63;
            if (rr < nrows) {
                int n = rows_sh[rr], b = n >> 12, hw = n & (HW - 1);
                ze[rr * 66 + k] = z[(size_t)b * CHW + k * HW + hw];
            }
        }
        __syncthreads();

        ULL best = ~0ULL;
        for (int ch = 0; ch < 8; ch++) {
            #pragma unroll
            for (int i = 0; i < 32; i++) {
                int f = tid + 256 * i;
                int code = f >> 6, k = f & 63;
                es[code * 65 + k] = emb[ch * 8192 + f];
            }
            __syncthreads();
            if (r < nrows) {
                float S[8];
                #pragma unroll
                for (int j = 0; j < 8; j++) S[j] = 0.f;
                #pragma unroll 8
                for (int k = 0; k < 64; k++) {
                    float zk = ze[r * 66 + k];
                    #pragma unroll
                    for (int j = 0; j < 8; j++)
                        S[j] = __fmaf_rn(zk, es[(cc + 16 * j) * 65 + k], S[j]);
                }
                float zn = zn_sh[r];
                #pragma unroll
                for (int j = 0; j < 8; j++) {
                    int code = ch * 128 + cc + 16 * j;
                    float d = __fadd_rn(__fadd_rn(zn, __fmul_rn(-2.0f, S[j])), g_enorm[code]);
                    ULL key = ((ULL)__float_as_uint(d) << 32) | (unsigned)code;
                    if (key < best) best = key;
                }
            }
            __syncthreads();
        }
        #pragma unroll
        for (int m = 1; m < 16; m <<= 1) {
            ULL o = __shfl_xor_sync(0xffffffffu, best, m);
            best = u64min(best, o);
        }
        if (cc == 0 && r < nrows) g_idx[rows_sh[r]] = (int)(best & 0xffffffffULL);
        __syncthreads();
    }
}

// ---------------------------------------------------------------------------
// Kernel 2: gather + straight-through output + loss (fused last-block finish).
// 4 threads/row x 16 channels; e rows loaded as float4. (Unchanged; R11.)
// ---------------------------------------------------------------------------
__global__ __launch_bounds__(256) void gather_kernel(const float* __restrict__ z,
                                                     const float* __restrict__ emb,
                                                     float* __restrict__ out) {
    const int tid = threadIdx.x;
    const int m   = tid & 63;
    const int cg  = tid >> 6;
    const int n   = blockIdx.x * 64 + m;
    const int b   = n >> 12, hw = n & (HW - 1);
    const float* zp = z + (size_t)b * CHW + hw;
    float* op = out + (size_t)b * CHW + hw;
    const int idx = g_idx[n];
    const float4* e4 = (const float4*)(emb + idx * C + cg * 16);

    double s = 0.0;
    #pragma unroll
    for (int j = 0; j < 4; j++) {
        float4 q4 = __ldg(e4 + j);
        float qv[4] = {q4.x, q4.y, q4.z, q4.w};
        #pragma unroll
        for (int t = 0; t < 4; t++) {
            int c = cg * 16 + 4 * j + t;
            float zv   = zp[c * HW];
            float diff = __fadd_rn(qv[t], -zv);
            float qst  = __fadd_rn(zv, diff);
            op[c * HW] = qst;
            s += (double)__fmul_rn(diff, diff);
        }
    }

    __shared__ double sd[256];
    __shared__ bool s_last;
    sd[tid] = s;
    __syncthreads();
    for (int st = 128; st > 0; st >>= 1) {
        if (tid < st) sd[tid] += sd[tid + st];
        __syncthreads();
    }
    if (tid == 0) {
        g_partials[blockIdx.x] = sd[0];
        __threadfence();
        int t = atomicAdd(&g_gather_done, 1);
        s_last = (t == (int)gridDim.x - 1);
    }
    __syncthreads();

    if (s_last) {
        double s2 = 0.0;
        #pragma unroll
        for (int i = 0; i < 4; i++) s2 += g_partials[tid + 256 * i];
        sd[tid] = s2;
        __syncthreads();
        for (int st = 128; st > 0; st >>= 1) {
            if (tid < st) sd[tid] += sd[tid + st];
            __syncthreads();
        }
        if (tid == 0) {
            float mm = (float)(sd[0] / (double)((size_t)N * C));
            out[(size_t)N * C] = __fadd_rn(mm, 0.25f * mm);
        }
    }
}

// ---------------------------------------------------------------------------
extern "C" void kernel_launch(void* const* d_in, const int* in_sizes, int n_in,
                              void* d_out, int out_size) {
    const float* z   = (const float*)d_in[0];   // [16,64,64,64]
    const float* emb = (const float*)d_in[1];   // [1024,64]
    float* out = (float*)d_out;                 // 4194304 q_st + 1 loss

    cudaFuncSetAttribute(argmin_kernel,
                         cudaFuncAttributeMaxDynamicSharedMemorySize, SMEM_BYTES);

    prep_kernel  <<< K / 8, 256 >>>(emb);       // 128 blocks x 8 codes = 1024
    argmin_kernel<<< N / TM, 256, SMEM_BYTES >>>(z);
    repair_kernel<<< 128, 256 >>>(z, emb);
    gather_kernel<<< N / 64, 256 >>>(z, emb, out);
}